// round 4
// baseline (speedup 1.0000x reference)
#include <cuda_runtime.h>

#define BT    65536
#define KM    31
#define BLK   128
#define ROWS  512          // rows per block (4 per thread)
#define XSTR  513          // x tile stride (conflict-free padding)

// smem float offsets
#define W1T 0
#define B1  768
#define W2T 792
#define B2  1368
#define W3T 1392
#define B3  1968
#define W4T 1992
#define B4  2040
#define XS  2048
#define SMEM_FLOATS (XS + 32 * XSTR)   // 73856 B

typedef unsigned long long ull;

__device__ float g_s[KM * BT];

// ---------------- f32x2 helpers ----------------
__device__ __forceinline__ ull ffma2(ull a, ull b, ull c) {
    ull d; asm("fma.rn.f32x2 %0, %1, %2, %3;" : "=l"(d) : "l"(a), "l"(b), "l"(c)); return d;
}
__device__ __forceinline__ ull fmul2(ull a, ull b) {
    ull d; asm("mul.rn.f32x2 %0, %1, %2;" : "=l"(d) : "l"(a), "l"(b)); return d;
}
__device__ __forceinline__ ull dup2(float a) {
    ull d; asm("mov.b64 %0, {%1, %1};" : "=l"(d) : "f"(a)); return d;
}
__device__ __forceinline__ ull dup_lo(ull v) {
    ull d; asm("{\n\t.reg .b32 l, h;\n\tmov.b64 {l, h}, %1;\n\tmov.b64 %0, {l, l};\n\t}"
               : "=l"(d) : "l"(v)); return d;
}
__device__ __forceinline__ ull dup_hi(ull v) {
    ull d; asm("{\n\t.reg .b32 l, h;\n\tmov.b64 {l, h}, %1;\n\tmov.b64 %0, {h, h};\n\t}"
               : "=l"(d) : "l"(v)); return d;
}
__device__ __forceinline__ void unpack2(ull v, float& lo, float& hi) {
    asm("mov.b64 {%0, %1}, %2;" : "=f"(lo), "=f"(hi) : "l"(v));
}
// packed LeakyReLU(0.2): lrelu(v) = 0.6*v + 0.4*|v|
__device__ __forceinline__ ull lrelu2(ull v) {
    const ull C06 = 0x3F19999A3F19999AULL;
    const ull C04 = 0x3ECCCCCD3ECCCCCDULL;
    const ull MSK = 0x7FFFFFFF7FFFFFFFULL;
    return ffma2(C04, v & MSK, fmul2(C06, v));
}

// One 24->24 layer for 4 rows. P = PRE-activations of previous layer
// (lrelu applied on the fly at consumption). Q = pre-activations out.
// Only P and Q are live (no third array).
__device__ __forceinline__ void layer24f(const ull (*P)[12], ull (*Q)[12],
                                         const float* wt, const float* bias)
{
    const ull* bp = (const ull*)bias;
    #pragma unroll
    for (int p = 0; p < 12; ++p) {
        const ull b = bp[p];
        #pragma unroll
        for (int r = 0; r < 4; ++r) Q[r][p] = b;
    }
    #pragma unroll
    for (int hp = 0; hp < 12; ++hp) {
        ull de[4], dh[4];
        #pragma unroll
        for (int r = 0; r < 4; ++r) {
            const ull a = lrelu2(P[r][hp]);     // P[r][hp] dies here
            de[r] = dup_lo(a); dh[r] = dup_hi(a);
        }
        const ulonglong2* we = (const ulonglong2*)(wt + (2 * hp)     * 24);
        const ulonglong2* wo = (const ulonglong2*)(wt + (2 * hp + 1) * 24);
        #pragma unroll
        for (int q = 0; q < 6; ++q) {
            const ulonglong2 a = we[q];
            #pragma unroll
            for (int r = 0; r < 4; ++r) {
                Q[r][2*q]   = ffma2(a.x, de[r], Q[r][2*q]);
                Q[r][2*q+1] = ffma2(a.y, de[r], Q[r][2*q+1]);
            }
            const ulonglong2 b = wo[q];
            #pragma unroll
            for (int r = 0; r < 4; ++r) {
                Q[r][2*q]   = ffma2(b.x, dh[r], Q[r][2*q]);
                Q[r][2*q+1] = ffma2(b.y, dh[r], Q[r][2*q+1]);
            }
        }
    }
}

// ---------------- main kernel: one (k, 512-row tile) per block ----------------
__global__ __launch_bounds__(BLK, 2)
void maf_main(const float* __restrict__ x,
              const float* __restrict__ W1, const float* __restrict__ b1,
              const float* __restrict__ W2, const float* __restrict__ b2,
              const float* __restrict__ W3, const float* __restrict__ b3,
              const float* __restrict__ W4, const float* __restrict__ b4,
              float* __restrict__ out)
{
    extern __shared__ __align__(16) float sm[];

    const int tid  = threadIdx.x;
    const int k    = blockIdx.y;
    const int base = blockIdx.x * ROWS;

    // ---- stage weights (transposed: output-pairs contiguous) ----
    {
        const float* gW1 = W1 + k * 768;
        for (int i = tid; i < 768; i += BLK) {
            const int h = i >> 5, j = i & 31;
            sm[W1T + j * 24 + h] = gW1[i];
        }
        const float* gW2 = W2 + k * 576;
        for (int i = tid; i < 576; i += BLK)
            sm[W2T + (i % 24) * 24 + (i / 24)] = gW2[i];
        const float* gW3 = W3 + k * 576;
        for (int i = tid; i < 576; i += BLK)
            sm[W3T + (i % 24) * 24 + (i / 24)] = gW3[i];
        const float* gW4 = W4 + k * 48;
        for (int i = tid; i < 48; i += BLK)
            sm[W4T + (i % 24) * 2 + (i / 24)] = gW4[i];
        if (tid < 24) {
            sm[B1 + tid] = b1[k * 24 + tid];
            sm[B2 + tid] = b2[k * 24 + tid];
            sm[B3 + tid] = b3[k * 24 + tid];
        }
        if (tid < 2) sm[B4 + tid] = b4[k * 2 + tid];
    }
    // ---- stage x tile, transposed to [j][row], stride 513 (conflict-free) ----
    for (int it = tid; it < ROWS * 8; it += BLK) {
        const int r  = it >> 3;
        const int jc = it & 7;
        const float4 v = ((const float4*)x)[(size_t)(base + r) * 8 + jc];
        sm[XS + (4*jc + 0) * XSTR + r] = v.x;
        sm[XS + (4*jc + 1) * XSTR + r] = v.y;
        sm[XS + (4*jc + 2) * XSTR + r] = v.z;
        sm[XS + (4*jc + 3) * XSTR + r] = v.w;
    }
    __syncthreads();

    ull A[4][12], B[4][12];   // the only two big arrays (96 regs each)

    // ---- layer 1: (k+1) -> 24, pre-activations into A ----
    {
        const ull* bp = (const ull*)(sm + B1);
        #pragma unroll
        for (int p = 0; p < 12; ++p) {
            const ull b = bp[p];
            #pragma unroll
            for (int r = 0; r < 4; ++r) A[r][p] = b;
        }
        #pragma unroll 2
        for (int j = 0; j <= k; ++j) {
            ull d[4];
            #pragma unroll
            for (int r = 0; r < 4; ++r)
                d[r] = dup2(sm[XS + j * XSTR + tid + 128 * r]);
            const ulonglong2* w = (const ulonglong2*)(sm + W1T + j * 24);
            #pragma unroll
            for (int q = 0; q < 6; ++q) {
                const ulonglong2 wq = w[q];
                #pragma unroll
                for (int r = 0; r < 4; ++r) {
                    A[r][2*q]   = ffma2(wq.x, d[r], A[r][2*q]);
                    A[r][2*q+1] = ffma2(wq.y, d[r], A[r][2*q+1]);
                }
            }
        }
    }

    // ---- layers 2 & 3 (lrelu fused at consumption; ping-pong A<->B) ----
    layer24f(A, B, sm + W2T, sm + B2);
    layer24f(B, A, sm + W3T, sm + B3);

    // ---- layer 4: 24 -> (s, t) ----
    ull st[4];
    {
        const ull b4v = *(const ull*)(sm + B4);
        #pragma unroll
        for (int r = 0; r < 4; ++r) st[r] = b4v;
        const ull* w4 = (const ull*)(sm + W4T);
        #pragma unroll
        for (int hp = 0; hp < 12; ++hp) {
            const ull we = w4[2*hp], wo = w4[2*hp + 1];
            #pragma unroll
            for (int r = 0; r < 4; ++r) {
                const ull a = lrelu2(A[r][hp]);
                st[r] = ffma2(we, dup_lo(a), st[r]);
                st[r] = ffma2(wo, dup_hi(a), st[r]);
            }
        }
    }

    // ---- epilogue: z[:, 30-k] = x[:, k+1]*exp(s)+t ; s -> g_s ----
    #pragma unroll
    for (int r = 0; r < 4; ++r) {
        float s, t;
        unpack2(st[r], s, t);
        const int row = tid + 128 * r;
        const float xk = sm[XS + (k + 1) * XSTR + row];
        const int gr = base + row;
        out[(size_t)gr * 32 + (30 - k)] = xk * expf(s) + t;
        g_s[k * BT + gr] = s;
    }
}

// ---------------- log_det reduce + dim-0 leaf (4 rows/thread, float4) ----------------
__global__ void reduce_kernel(const float* __restrict__ x,
                              const float* __restrict__ p0,
                              float* __restrict__ out)
{
    const int t = blockIdx.x * 128 + threadIdx.x;   // 16384 threads, 4 rows each
    const float s0 = p0[0];
    const float e0 = expf(s0);
    const float t0 = p0[1];
    float4 sum = make_float4(s0, s0, s0, s0);
    #pragma unroll
    for (int kk = 0; kk < KM; ++kk) {
        const float4 v = ((const float4*)(g_s + kk * BT))[t];
        sum.x += v.x; sum.y += v.y; sum.z += v.z; sum.w += v.w;
    }
    ((float4*)(out + (size_t)BT * 32))[t] = sum;     // log_det
    #pragma unroll
    for (int r = 0; r < 4; ++r) {
        const int b = 4 * t + r;
        out[(size_t)b * 32 + 31] = x[(size_t)b * 32] * e0 + t0;   // z col 31
    }
}

extern "C" void kernel_launch(void* const* d_in, const int* in_sizes, int n_in,
                              void* d_out, int out_size)
{
    const float* x  = (const float*)d_in[0];
    const float* p0 = (const float*)d_in[1];
    const float* W1 = (const float*)d_in[2];
    const float* b1 = (const float*)d_in[3];
    const float* W2 = (const float*)d_in[4];
    const float* b2 = (const float*)d_in[5];
    const float* W3 = (const float*)d_in[6];
    const float* b3 = (const float*)d_in[7];
    const float* W4 = (const float*)d_in[8];
    const float* b4 = (const float*)d_in[9];
    float* out = (float*)d_out;

    const int smem_bytes = SMEM_FLOATS * 4;
    cudaFuncSetAttribute(maf_main, cudaFuncAttributeMaxDynamicSharedMemorySize, smem_bytes);

    maf_main<<<dim3(BT / ROWS, KM), BLK, smem_bytes>>>(x, W1, b1, W2, b2, W3, b3, W4, b4, out);
    reduce_kernel<<<BT / 512, 128>>>(x, p0, out);
}

// round 5
// speedup vs baseline: 1.0484x; 1.0484x over previous
#include <cuda_runtime.h>

#define BT    65536
#define KM    31
#define BLK   128
#define ROWS  256          // rows per block (2 per thread)
#define XSTR  257          // x tile stride (conflict-free)

// smem float offsets
#define W1T 0
#define B1  768
#define W2T 792
#define B2  1368
#define W3T 1392
#define B3  1968
#define W4T 1992
#define B4  2040
#define XS  2048
#define SMEM_FLOATS (XS + 32 * XSTR)   // 10272 floats = 41088 B

typedef unsigned long long ull;

__device__ float g_s[KM * BT];

// ---------------- f32x2 helpers ----------------
__device__ __forceinline__ ull ffma2(ull a, ull b, ull c) {
    ull d; asm("fma.rn.f32x2 %0, %1, %2, %3;" : "=l"(d) : "l"(a), "l"(b), "l"(c)); return d;
}
__device__ __forceinline__ ull fmul2(ull a, ull b) {
    ull d; asm("mul.rn.f32x2 %0, %1, %2;" : "=l"(d) : "l"(a), "l"(b)); return d;
}
__device__ __forceinline__ ull dup2(float a) {
    ull d; asm("mov.b64 %0, {%1, %1};" : "=l"(d) : "f"(a)); return d;
}
__device__ __forceinline__ ull dup_lo(ull v) {
    ull d; asm("{\n\t.reg .b32 l, h;\n\tmov.b64 {l, h}, %1;\n\tmov.b64 %0, {l, l};\n\t}"
               : "=l"(d) : "l"(v)); return d;
}
__device__ __forceinline__ ull dup_hi(ull v) {
    ull d; asm("{\n\t.reg .b32 l, h;\n\tmov.b64 {l, h}, %1;\n\tmov.b64 %0, {h, h};\n\t}"
               : "=l"(d) : "l"(v)); return d;
}
__device__ __forceinline__ void unpack2(ull v, float& lo, float& hi) {
    asm("mov.b64 {%0, %1}, %2;" : "=f"(lo), "=f"(hi) : "l"(v));
}
// packed LeakyReLU(0.2): 0.6*v + 0.4*|v|
__device__ __forceinline__ ull lrelu2(ull v) {
    const ull C06 = 0x3F19999A3F19999AULL;
    const ull C04 = 0x3ECCCCCD3ECCCCCDULL;
    const ull MSK = 0x7FFFFFFF7FFFFFFFULL;
    return ffma2(C04, v & MSK, fmul2(C06, v));
}

// 24->24 layer for 2 rows, computed in OUTPUT HALVES (6 pairs at a time) to
// cap register liveness at ~(P:48 + Qhalf:12 + temps). P holds POST-lrelu
// activations; Q receives post-lrelu activations.
__device__ __forceinline__ void layer24h(const ull* __restrict__ P0, const ull* __restrict__ P1,
                                         ull* __restrict__ Q0, ull* __restrict__ Q1,
                                         const float* wt, const float* bias)
{
    const ull* bp = (const ull*)bias;
    #pragma unroll
    for (int half = 0; half < 2; ++half) {
        ull q0[6], q1[6];
        #pragma unroll
        for (int p = 0; p < 6; ++p) { q0[p] = bp[half * 6 + p]; q1[p] = q0[p]; }
        #pragma unroll
        for (int hp = 0; hp < 12; ++hp) {
            const ull de0 = dup_lo(P0[hp]), dh0 = dup_hi(P0[hp]);
            const ull de1 = dup_lo(P1[hp]), dh1 = dup_hi(P1[hp]);
            const ulonglong2* we = (const ulonglong2*)(wt + (2*hp)     * 24 + half * 12);
            const ulonglong2* wo = (const ulonglong2*)(wt + (2*hp + 1) * 24 + half * 12);
            #pragma unroll
            for (int q = 0; q < 3; ++q) {
                const ulonglong2 a = we[q];
                q0[2*q]   = ffma2(a.x, de0, q0[2*q]);
                q1[2*q]   = ffma2(a.x, de1, q1[2*q]);
                q0[2*q+1] = ffma2(a.y, de0, q0[2*q+1]);
                q1[2*q+1] = ffma2(a.y, de1, q1[2*q+1]);
                const ulonglong2 b = wo[q];
                q0[2*q]   = ffma2(b.x, dh0, q0[2*q]);
                q1[2*q]   = ffma2(b.x, dh1, q1[2*q]);
                q0[2*q+1] = ffma2(b.y, dh0, q0[2*q+1]);
                q1[2*q+1] = ffma2(b.y, dh1, q1[2*q+1]);
            }
        }
        #pragma unroll
        for (int p = 0; p < 6; ++p) {
            Q0[half * 6 + p] = lrelu2(q0[p]);
            Q1[half * 6 + p] = lrelu2(q1[p]);
        }
    }
}

// ---------------- main kernel: one (k, 256-row tile) per block ----------------
__global__ __launch_bounds__(BLK, 5)
void maf_main(const float* __restrict__ x,
              const float* __restrict__ W1, const float* __restrict__ b1,
              const float* __restrict__ W2, const float* __restrict__ b2,
              const float* __restrict__ W3, const float* __restrict__ b3,
              const float* __restrict__ W4, const float* __restrict__ b4,
              float* __restrict__ out)
{
    extern __shared__ __align__(16) float sm[];

    const int tid  = threadIdx.x;
    const int k    = blockIdx.y;
    const int base = blockIdx.x * ROWS;

    // ---- stage weights (transposed: output-pairs contiguous) ----
    {
        const float* gW1 = W1 + k * 768;
        for (int i = tid; i < 768; i += BLK) {
            const int h = i >> 5, j = i & 31;
            sm[W1T + j * 24 + h] = gW1[i];
        }
        const float* gW2 = W2 + k * 576;
        for (int i = tid; i < 576; i += BLK)
            sm[W2T + (i % 24) * 24 + (i / 24)] = gW2[i];
        const float* gW3 = W3 + k * 576;
        for (int i = tid; i < 576; i += BLK)
            sm[W3T + (i % 24) * 24 + (i / 24)] = gW3[i];
        const float* gW4 = W4 + k * 48;
        for (int i = tid; i < 48; i += BLK)
            sm[W4T + (i % 24) * 2 + (i / 24)] = gW4[i];
        if (tid < 24) {
            sm[B1 + tid] = b1[k * 24 + tid];
            sm[B2 + tid] = b2[k * 24 + tid];
            sm[B3 + tid] = b3[k * 24 + tid];
        }
        if (tid < 2) sm[B4 + tid] = b4[k * 2 + tid];
    }
    // ---- stage x tile cols 0..k+1, transposed to [j][row], stride 257 ----
    {
        const int jcmax = (k + 1) >> 2;            // need cols 0..k+1
        for (int it = tid; it < ROWS * 8; it += BLK) {
            const int jc = it & 7;
            if (jc <= jcmax) {
                const int r = it >> 3;
                const float4 v = ((const float4*)x)[(size_t)(base + r) * 8 + jc];
                sm[XS + (4*jc + 0) * XSTR + r] = v.x;
                sm[XS + (4*jc + 1) * XSTR + r] = v.y;
                sm[XS + (4*jc + 2) * XSTR + r] = v.z;
                sm[XS + (4*jc + 3) * XSTR + r] = v.w;
            }
        }
    }
    __syncthreads();

    ull A0[12], A1[12], B0[12], B1r[12];

    // ---- layer 1: (k+1) -> 24 -> post-lrelu into A ----
    {
        const ull* bp = (const ull*)(sm + B1);
        #pragma unroll
        for (int p = 0; p < 12; ++p) { A0[p] = bp[p]; A1[p] = bp[p]; }
        #pragma unroll 2
        for (int j = 0; j <= k; ++j) {
            const ull d0 = dup2(sm[XS + j * XSTR + tid]);
            const ull d1 = dup2(sm[XS + j * XSTR + tid + 128]);
            const ulonglong2* w = (const ulonglong2*)(sm + W1T + j * 24);
            #pragma unroll
            for (int q = 0; q < 6; ++q) {
                const ulonglong2 wq = w[q];
                A0[2*q]   = ffma2(wq.x, d0, A0[2*q]);
                A1[2*q]   = ffma2(wq.x, d1, A1[2*q]);
                A0[2*q+1] = ffma2(wq.y, d0, A0[2*q+1]);
                A1[2*q+1] = ffma2(wq.y, d1, A1[2*q+1]);
            }
        }
        #pragma unroll
        for (int p = 0; p < 12; ++p) { A0[p] = lrelu2(A0[p]); A1[p] = lrelu2(A1[p]); }
    }

    // ---- layers 2 & 3 (half-split, ping-pong) ----
    layer24h(A0, A1, B0, B1r, sm + W2T, sm + B2);
    layer24h(B0, B1r, A0, A1, sm + W3T, sm + B3);

    // ---- layer 4: 24 -> (s, t) ----
    ull st0, st1;
    {
        st0 = *(const ull*)(sm + B4);
        st1 = st0;
        const ull* w4 = (const ull*)(sm + W4T);
        #pragma unroll
        for (int hp = 0; hp < 12; ++hp) {
            const ull we = w4[2*hp], wo = w4[2*hp + 1];
            st0 = ffma2(we, dup_lo(A0[hp]), st0);
            st1 = ffma2(we, dup_lo(A1[hp]), st1);
            st0 = ffma2(wo, dup_hi(A0[hp]), st0);
            st1 = ffma2(wo, dup_hi(A1[hp]), st1);
        }
    }

    // ---- epilogue ----
    {
        float s, t;
        unpack2(st0, s, t);
        const float xk = sm[XS + (k + 1) * XSTR + tid];
        const int gr = base + tid;
        out[(size_t)gr * 32 + (30 - k)] = xk * expf(s) + t;
        g_s[k * BT + gr] = s;
    }
    {
        float s, t;
        unpack2(st1, s, t);
        const float xk = sm[XS + (k + 1) * XSTR + tid + 128];
        const int gr = base + tid + 128;
        out[(size_t)gr * 32 + (30 - k)] = xk * expf(s) + t;
        g_s[k * BT + gr] = s;
    }
}

// ---------------- log_det reduce + dim-0 leaf ----------------
__global__ void reduce_kernel(const float* __restrict__ x,
                              const float* __restrict__ p0,
                              float* __restrict__ out)
{
    const int b = blockIdx.x * 256 + threadIdx.x;
    const float s0 = p0[0];
    float sum = s0;
    #pragma unroll
    for (int kk = 0; kk < KM; ++kk) sum += g_s[kk * BT + b];
    out[(size_t)BT * 32 + b] = sum;                                   // log_det
    out[(size_t)b * 32 + 31] = x[(size_t)b * 32] * expf(s0) + p0[1];  // z col 31
}

extern "C" void kernel_launch(void* const* d_in, const int* in_sizes, int n_in,
                              void* d_out, int out_size)
{
    const float* x  = (const float*)d_in[0];
    const float* p0 = (const float*)d_in[1];
    const float* W1 = (const float*)d_in[2];
    const float* b1 = (const float*)d_in[3];
    const float* W2 = (const float*)d_in[4];
    const float* b2 = (const float*)d_in[5];
    const float* W3 = (const float*)d_in[6];
    const float* b3 = (const float*)d_in[7];
    const float* W4 = (const float*)d_in[8];
    const float* b4 = (const float*)d_in[9];
    float* out = (float*)d_out;

    const int smem_bytes = SMEM_FLOATS * 4;
    cudaFuncSetAttribute(maf_main, cudaFuncAttributeMaxDynamicSharedMemorySize, smem_bytes);

    maf_main<<<dim3(BT / ROWS, KM), BLK, smem_bytes>>>(x, W1, b1, W2, b2, W3, b3, W4, b4, out);
    reduce_kernel<<<BT / 256, 256>>>(x, p0, out);
}